// round 8
// baseline (speedup 1.0000x reference)
#include <cuda_runtime.h>
#include <cuda_bf16.h>
#include <math.h>
#include <cstdint>

// Problem constants
#define Bz   128
#define Kz   128
#define Dz   512
#define Lz   2
#define DIz  1024
#define Mz   (Bz*Kz)        // 16384 rows
#define HWz  4096

// GEMM tiling: CTA 256 threads, tile 128x256, 8 warps of 64x64 (2m x 4n), BK=32
#define BM 128
#define BN 256
#define BK 32
#define ASTR 36
#define BSTR 264
#define A_TILE_F (BM*ASTR)                      // 4608
#define B_TILE_F (BK*BSTR)                      // 8448
#define STAGE_F  (A_TILE_F + B_TILE_F)          // 13056
#define DSMEM_BYTES (2*STAGE_F*4)               // 104448 B

// ---------------- scratch globals -------------------------------------------
__device__ float g_x   [Mz*Dz];
__device__ float g_lnf [Mz*Dz];
__device__ float g_h   [Mz*2048];       // GLU out / ffn1 out
__device__ float g_res [Mz*Dz];
__device__ float g_enc [Mz*256];
__device__ float g_cent[Mz*2];
// precomputed weights/biases
__device__ float g_wcat[2*512*4096];    // folded+permuted in-proj (z/gate interleaved)
__device__ float g_bcat[2*4096];
__device__ float g_wmid[2*2560*512];    // [WfoMt ; WboMb ; Mt+Mb]
__device__ float g_bmid[2*512];
__device__ float g_wf1 [2*512*2048];    // folded ffn1
__device__ float g_bf1 [2*2048];
__device__ float g_zero[512];           // zero bias (static zero-init)

// ---------------- helpers ---------------------------------------------------
__device__ __forceinline__ uint32_t smem_u32(const void* p){
  uint32_t a;
  asm("{ .reg .u64 t; cvta.to.shared.u64 t, %1; cvt.u32.u64 %0, t; }" : "=r"(a) : "l"(p));
  return a;
}
__device__ __forceinline__ void cpa16(void* dst, const void* src){
  asm volatile("cp.async.cg.shared.global [%0], [%1], 16;"
               :: "r"(smem_u32(dst)), "l"(src) : "memory");
}
__device__ __forceinline__ void cpa_commit(){
  asm volatile("cp.async.commit_group;" ::: "memory");
}
template<int N> __device__ __forceinline__ void cpa_wait(){
  asm volatile("cp.async.wait_group %0;" :: "n"(N) : "memory");
}
__device__ __forceinline__ void mma_tf32(float* d, const uint32_t* a, const uint32_t* b){
  asm volatile(
    "mma.sync.aligned.m16n8k8.row.col.f32.tf32.tf32.f32 "
    "{%0,%1,%2,%3}, {%4,%5,%6,%7}, {%8,%9}, {%0,%1,%2,%3};"
    : "+f"(d[0]), "+f"(d[1]), "+f"(d[2]), "+f"(d[3])
    : "r"(a[0]), "r"(a[1]), "r"(a[2]), "r"(a[3]), "r"(b[0]), "r"(b[1]));
}
__device__ __forceinline__ float tf32rna(float x){
  float r; asm("cvt.rna.tf32.f32 %0, %1;" : "=f"(r) : "f"(x)); return r;
}
__device__ __forceinline__ float gelu_exact(float x){
  return 0.5f * x * (1.0f + erff(x * 0.70710678118654752f));
}
__device__ __forceinline__ float sigmoidf(float x){
  return 1.0f / (1.0f + expf(-x));
}

// ---------------- tf32 mma GEMM: Out = act(Acat @ W + bias) [+Add][*mask] ----
// Acat = [A1 (K1 cols) | A2 (Ktot-K1 cols)], row-major with strides ld1/ld2.
// ACT: 0 none, 1 gelu, 2 GLU (silu(even)*sigmoid(odd) -> col ((n&2047)>>1)+(n>>11)*1024)
template<int ACT, bool HAS_ADD, bool HAS_MASK>
__global__ __launch_bounds__(256, 2) void gemm2(
    const float* __restrict__ A1, int ld1, int K1,
    const float* __restrict__ A2, int ld2, int Ktot,
    const float* __restrict__ W, int N,
    const float* __restrict__ bias,
    const float* __restrict__ Add, int ldadd,
    const float* __restrict__ mask,
    float* __restrict__ Out, int ldout)
{
  extern __shared__ float sm[];
  const int tid  = threadIdx.x;
  const int lane = tid & 31;
  const int warp = tid >> 5;          // 0..7
  const int wm   = warp & 1;          // 64-row half
  const int wn   = warp >> 1;         // 0..3: 64-col quarter
  const int m0 = blockIdx.y * BM;
  const int n0 = blockIdx.x * BN;

  float acc[4][8][4];
#pragma unroll
  for (int i=0;i<4;i++)
#pragma unroll
    for (int j=0;j<8;j++)
#pragma unroll
      for (int r=0;r<4;r++) acc[i][j][r]=0.f;

  const int nch = Ktot / BK;

  auto load_chunk = [&](int c, int buf){
    const int k0 = c*BK;
    const float* src; int ld;
    if (k0 < K1){ src = A1 + (size_t)m0*ld1 + k0; ld = ld1; }
    else        { src = A2 + (size_t)m0*ld2 + (k0 - K1); ld = ld2; }
    float* sA = sm + buf*STAGE_F;
    float* sB = sA + A_TILE_F;
    const float* Wb = W + (size_t)k0*N + n0;
#pragma unroll
    for (int i=0;i<4;i++){                 // A: 128 rows x 32 floats
      int idx = tid + i*256;
      int m  = idx >> 3;
      int k4 = idx & 7;
      cpa16(sA + m*ASTR + k4*4, src + (size_t)m*ld + k4*4);
    }
#pragma unroll
    for (int i=0;i<8;i++){                 // B: 32 rows x 256 floats
      int idx = tid + i*256;
      int r  = idx >> 6;
      int c4 = idx & 63;
      cpa16(sB + r*BSTR + c4*4, Wb + (size_t)r*N + c4*4);
    }
    cpa_commit();
  };

  load_chunk(0, 0);

  for (int c = 0; c < nch; c++){
    const int buf = c & 1;
    if (c+1 < nch){ load_chunk(c+1, (c+1)&1); cpa_wait<1>(); }
    else          { cpa_wait<0>(); }
    __syncthreads();

    const float* sA = sm + buf*STAGE_F;
    const float* sB = sA + A_TILE_F;

#pragma unroll
    for (int ks = 0; ks < BK/8; ks++){
      uint32_t afr[4][4];
#pragma unroll
      for (int mi=0;mi<4;mi++){
        int r  = wm*64 + mi*16 + (lane>>2);
        int cc = ks*8 + (lane&3);
        afr[mi][0] = __float_as_uint(sA[r*ASTR + cc]);
        afr[mi][1] = __float_as_uint(sA[(r+8)*ASTR + cc]);
        afr[mi][2] = __float_as_uint(sA[r*ASTR + cc + 4]);
        afr[mi][3] = __float_as_uint(sA[(r+8)*ASTR + cc + 4]);
      }
      uint32_t bfr[8][2];
#pragma unroll
      for (int nj=0;nj<8;nj++){
        int rr = ks*8 + (lane&3);
        int cc = wn*64 + nj*8 + (lane>>2);
        bfr[nj][0] = __float_as_uint(sB[rr*BSTR + cc]);
        bfr[nj][1] = __float_as_uint(sB[(rr+4)*BSTR + cc]);
      }
#pragma unroll
      for (int mi=0;mi<4;mi++)
#pragma unroll
        for (int nj=0;nj<8;nj++)
          mma_tf32(acc[mi][nj], afr[mi], bfr[nj]);
    }
    __syncthreads();
  }

  // ---- epilogue ----
#pragma unroll
  for (int mi=0;mi<4;mi++){
    const int r0 = m0 + wm*64 + mi*16 + (lane>>2);
    const int r1 = r0 + 8;
    const float mk0 = HAS_MASK ? mask[r0] : 1.f;
    const float mk1 = HAS_MASK ? mask[r1] : 1.f;
#pragma unroll
    for (int nj=0;nj<8;nj++){
      const int cb = n0 + wn*64 + nj*8 + (lane&3)*2;
      const float b0 = bias[cb], b1 = bias[cb+1];
      float v0 = acc[mi][nj][0] + b0;
      float v1 = acc[mi][nj][1] + b1;
      float v2 = acc[mi][nj][2] + b0;
      float v3 = acc[mi][nj][3] + b1;
      if (ACT == 2){
        const int oc = ((cb & 2047) >> 1) + (cb >> 11)*1024;
        Out[(size_t)r0*ldout + oc] = v0 * sigmoidf(v0) * sigmoidf(v1);
        Out[(size_t)r1*ldout + oc] = v2 * sigmoidf(v2) * sigmoidf(v3);
      } else {
        if (ACT == 1){
          v0 = gelu_exact(v0); v1 = gelu_exact(v1);
          v2 = gelu_exact(v2); v3 = gelu_exact(v3);
        }
        if (HAS_ADD){
          v0 += Add[(size_t)r0*ldadd + cb];   v1 += Add[(size_t)r0*ldadd + cb+1];
          v2 += Add[(size_t)r1*ldadd + cb];   v3 += Add[(size_t)r1*ldadd + cb+1];
        }
        if (HAS_MASK){ v0*=mk0; v1*=mk0; v2*=mk1; v3*=mk1; }
        *(float2*)&Out[(size_t)r0*ldout + cb] = make_float2(v0, v1);
        *(float2*)&Out[(size_t)r1*ldout + cb] = make_float2(v2, v3);
      }
    }
  }
}

// ---------------- LayerNorm kernels (D=512) ---------------------------------
__device__ __forceinline__ float block_sum_128(float v, volatile float* sh){
#pragma unroll
  for (int o=16;o>0;o>>=1) v += __shfl_xor_sync(0xffffffffu, v, o);
  int w = threadIdx.x >> 5;
  if ((threadIdx.x & 31)==0) sh[w] = v;
  __syncthreads();
  float r = sh[0]+sh[1]+sh[2]+sh[3];
  __syncthreads();
  return r;
}

__global__ __launch_bounds__(128) void ln_plain_kernel(
  const float* __restrict__ X, float* __restrict__ Y)
{
  __shared__ float sh[4];
  int row = blockIdx.x, t = threadIdx.x;
  float4 v = ((const float4*)(X + (size_t)row*Dz))[t];
  float s = block_sum_128(v.x+v.y+v.z+v.w, sh);
  float mean = s * (1.0f/Dz);
  float dx=v.x-mean, dy=v.y-mean, dz=v.z-mean, dw=v.w-mean;
  float sq = block_sum_128(dx*dx+dy*dy+dz*dz+dw*dw, sh);
  float inv = rsqrtf(sq*(1.0f/Dz) + 1e-5f);
  ((float4*)(Y + (size_t)row*Dz))[t] = make_float4(dx*inv, dy*inv, dz*inv, dw*inv);
}

__global__ __launch_bounds__(128) void ln_chain2_kernel(
  const float* __restrict__ X,
  const float* __restrict__ g, const float* __restrict__ b,
  float* __restrict__ Y1, float* __restrict__ Y2)
{
  __shared__ float sh[4];
  int row = blockIdx.x, t = threadIdx.x;
  float4 v = ((const float4*)(X + (size_t)row*Dz))[t];
  float s = block_sum_128(v.x+v.y+v.z+v.w, sh);
  float mean = s * (1.0f/Dz);
  float dx=v.x-mean, dy=v.y-mean, dz=v.z-mean, dw=v.w-mean;
  float sq = block_sum_128(dx*dx+dy*dy+dz*dz+dw*dw, sh);
  float inv = rsqrtf(sq*(1.0f/Dz) + 1e-5f);
  float4 G = ((const float4*)g)[t]; float4 Bb = ((const float4*)b)[t];
  float4 y = make_float4(dx*inv*G.x+Bb.x, dy*inv*G.y+Bb.y, dz*inv*G.z+Bb.z, dw*inv*G.w+Bb.w);
  ((float4*)(Y1 + (size_t)row*Dz))[t] = y;
  float s2 = block_sum_128(y.x+y.y+y.z+y.w, sh);
  float m2 = s2 * (1.0f/Dz);
  float ex=y.x-m2, ey=y.y-m2, ez=y.z-m2, ew=y.w-m2;
  float sq2 = block_sum_128(ex*ex+ey*ey+ez*ez+ew*ew, sh);
  float inv2 = rsqrtf(sq2*(1.0f/Dz) + 1e-5f);
  ((float4*)(Y2 + (size_t)row*Dz))[t] = make_float4(ex*inv2, ey*inv2, ez*inv2, ew*inv2);
}

// ---------------- centroids / enc -------------------------------------------
__global__ __launch_bounds__(256) void centroid_kernel(
  const float* __restrict__ attn, float* __restrict__ cent, float* __restrict__ cent_out)
{
  int bk = blockIdx.x;
  const float* a = attn + (size_t)bk*HWz;
  float s=0.f, sx=0.f, sy=0.f;
#pragma unroll 4
  for (int i=threadIdx.x; i<HWz; i+=256){
    float v = a[i];
    s  += v;
    sx += v * (float)(i & 63);
    sy += v * (float)(i >> 6);
  }
#pragma unroll
  for (int o=16;o>0;o>>=1){
    s  += __shfl_xor_sync(0xffffffffu, s,  o);
    sx += __shfl_xor_sync(0xffffffffu, sx, o);
    sy += __shfl_xor_sync(0xffffffffu, sy, o);
  }
  __shared__ float sh[24];
  int w = threadIdx.x >> 5;
  if ((threadIdx.x & 31)==0){ sh[w]=s; sh[8+w]=sx; sh[16+w]=sy; }
  __syncthreads();
  if (threadIdx.x==0){
    float S=0.f, SX=0.f, SY=0.f;
    for (int i=0;i<8;i++){ S+=sh[i]; SX+=sh[8+i]; SY+=sh[16+i]; }
    float invs = 1.0f/(S + 1e-8f);
    float cx = SX * (1.0f/63.0f) * invs;
    float cy = SY * (1.0f/63.0f) * invs;
    cent[bk*2]   = cx;
    cent[bk*2+1] = cy;
    if (cent_out){ cent_out[bk*2] = cx; cent_out[bk*2+1] = cy; }
  }
}

__global__ __launch_bounds__(256) void enc_kernel(
  const float* __restrict__ cent, float* __restrict__ E)
{
  int row = blockIdx.x, j = threadIdx.x;
  int f  = j >> 6;
  int jj = j & 63;
  int fi = jj & 31;
  float feat;
  if      (f==0) feat = cent[row*2];
  else if (f==1) feat = cent[row*2+1];
  else           feat = 0.1f;
  float freq = expf(-(float)fi * 0.28782313662425575f);
  float ang = feat * freq * 3.14159f;
  E[(size_t)row*256 + j] = (jj < 32) ? sinf(ang) : cosf(ang);
}

// ---------------- weight precompute kernels ---------------------------------
__global__ __launch_bounds__(256) void build_wcat(
  const float* __restrict__ fw, const float* __restrict__ bw,
  const float* __restrict__ fg, const float* __restrict__ bg)
{
  size_t idx = (size_t)blockIdx.x*256 + threadIdx.x;   // 2*512*4096
  int n = idx & 4095;
  int k = (idx >> 12) & 511;
  int i = (int)(idx >> 21);
  int br = n >> 11;
  int j2 = n & 2047;
  int src = (j2 & 1) ? 1024 + (j2 >> 1) : (j2 >> 1);
  const float* W = (br ? bw : fw) + (size_t)i*512*2048;
  const float* G = (br ? bg : fg) + i*512;
  g_wcat[idx] = tf32rna(G[k] * W[(size_t)k*2048 + src]);
}

// block-per-column bias reductions (R4-proven versions)
__global__ __launch_bounds__(128) void build_bcat(
  const float* __restrict__ fw, const float* __restrict__ bw,
  const float* __restrict__ fb, const float* __restrict__ bb,     // ln betas
  const float* __restrict__ fib, const float* __restrict__ bib)   // in biases
{
  int n = blockIdx.x;          // 0..4095
  int i = blockIdx.y;          // layer
  int br = n >> 11;
  int j2 = n & 2047;
  int src = (j2 & 1) ? 1024 + (j2 >> 1) : (j2 >> 1);
  const float* W   = (br ? bw : fw) + (size_t)i*512*2048;
  const float* LNB = (br ? bb : fb) + i*512;
  const float* INB = (br ? bib : fib) + i*2048;
  __shared__ float sh[4];
  float p = 0.f;
  for (int k = threadIdx.x; k < 512; k += 128)
    p += LNB[k] * W[(size_t)k*2048 + src];
  float tot = block_sum_128(p, sh);
  if (threadIdx.x == 0) g_bcat[i*4096 + n] = tot + INB[src];
}

__global__ __launch_bounds__(256) void build_wf1(
  const float* __restrict__ w1, const float* __restrict__ g)
{
  size_t idx = (size_t)blockIdx.x*256 + threadIdx.x;   // 2*512*2048
  int k = (int)((idx >> 11) & 511);
  int i = (int)(idx >> 20);
  g_wf1[idx] = tf32rna(g[i*512 + k] * w1[idx]);
}

__global__ __launch_bounds__(128) void build_bf1(
  const float* __restrict__ w1, const float* __restrict__ lnb,
  const float* __restrict__ b1)
{
  int n = blockIdx.x;          // 0..2047
  int i = blockIdx.y;
  const float* W = w1 + (size_t)i*512*2048;
  __shared__ float sh[4];
  float p = 0.f;
  for (int k = threadIdx.x; k < 512; k += 128)
    p += lnb[i*512 + k] * W[(size_t)k*2048 + n];
  float tot = block_sum_128(p, sh);
  if (threadIdx.x == 0) g_bf1[i*2048 + n] = tot + b1[i*2048 + n];
}

__global__ __launch_bounds__(256) void build_wmid_sum(const float* __restrict__ mw)
{
  size_t idx = (size_t)blockIdx.x*256 + threadIdx.x;   // 2*512*512
  int c = idx & 511;
  int k = (int)((idx >> 9) & 511);
  int i = (int)(idx >> 18);
  const float* Mt = mw + (size_t)i*1024*512;
  g_wmid[(size_t)i*2560*512 + (size_t)(2048 + k)*512 + c] =
      tf32rna(Mt[(size_t)k*512 + c] + Mt[(size_t)(512 + k)*512 + c]);
}

__global__ __launch_bounds__(128) void build_bmid(
  const float* __restrict__ mw, const float* __restrict__ mb,
  const float* __restrict__ fob, const float* __restrict__ bob)
{
  int c = blockIdx.x;          // 0..511
  int i = blockIdx.y;
  const float* Mt = mw + (size_t)i*1024*512;
  __shared__ float sh[4];
  float p = 0.f;
  for (int k = threadIdx.x; k < 512; k += 128){
    p += fob[i*512 + k] * Mt[(size_t)k*512 + c];
    p += bob[i*512 + k] * Mt[(size_t)(512 + k)*512 + c];
  }
  float tot = block_sum_128(p, sh);
  if (threadIdx.x == 0) g_bmid[i*512 + c] = tot + mb[i*512 + c];
}

// ---------------- host orchestration ----------------------------------------
extern "C" void kernel_launch(void* const* d_in, const int* in_sizes, int n_in,
                              void* d_out, int out_size)
{
  const float* slots     = (const float*)d_in[0];
  const float* keep      = (const float*)d_in[1];
  const float* attn      = (const float*)d_in[2];
  const float* pm1_w     = (const float*)d_in[5];
  const float* pm1_b     = (const float*)d_in[6];
  const float* pm2_w     = (const float*)d_in[7];
  const float* pm2_b     = (const float*)d_in[8];
  const float* fwd_ln_g  = (const float*)d_in[9];
  const float* fwd_ln_b  = (const float*)d_in[10];
  const float* fwd_in_w  = (const float*)d_in[11];
  const float* fwd_in_b  = (const float*)d_in[12];
  const float* fwd_out_w = (const float*)d_in[13];
  const float* fwd_out_b = (const float*)d_in[14];
  const float* bwd_ln_g  = (const float*)d_in[15];
  const float* bwd_ln_b  = (const float*)d_in[16];
  const float* bwd_in_w  = (const float*)d_in[17];
  const float* bwd_in_b  = (const float*)d_in[18];
  const float* bwd_out_w = (const float*)d_in[19];
  const float* bwd_out_b = (const float*)d_in[20];
  const float* merge_w   = (const float*)d_in[21];
  const float* merge_b   = (const float*)d_in[22];
  const float* norm_g    = (const float*)d_in[23];
  const float* norm_b    = (const float*)d_in[24];
  const float* ffn_ln_g  = (const float*)d_in[25];
  const float* ffn_ln_b  = (const float*)d_in[26];
  const float* ffn1_w    = (const float*)d_in[27];
  const float* ffn1_b    = (const float*)d_in[28];
  const float* ffn2_w    = (const float*)d_in[29];
  const float* ffn2_b    = (const float*)d_in[30];
  float* out = (float*)d_out;

  float *xg, *lnf, *hh, *res, *enc, *cent, *wcat, *bcat, *wmid, *bmid, *wf1, *bf1, *zb;
  cudaGetSymbolAddress((void**)&xg,   g_x);
  cudaGetSymbolAddress((void**)&lnf,  g_lnf);
  cudaGetSymbolAddress((void**)&hh,   g_h);
  cudaGetSymbolAddress((void**)&res,  g_res);
  cudaGetSymbolAddress((void**)&enc,  g_enc);
  cudaGetSymbolAddress((void**)&cent, g_cent);
  cudaGetSymbolAddress((void**)&wcat, g_wcat);
  cudaGetSymbolAddress((void**)&bcat, g_bcat);
  cudaGetSymbolAddress((void**)&wmid, g_wmid);
  cudaGetSymbolAddress((void**)&bmid, g_bmid);
  cudaGetSymbolAddress((void**)&wf1,  g_wf1);
  cudaGetSymbolAddress((void**)&bf1,  g_bf1);
  cudaGetSymbolAddress((void**)&zb,   g_zero);

  float* cent_out = nullptr;
  if ((long long)out_size >= (long long)Mz*Dz + (long long)Mz*2)
    cent_out = out + (size_t)Mz*Dz;

  cudaFuncSetAttribute(gemm2<0,false,false>, cudaFuncAttributeMaxDynamicSharedMemorySize, DSMEM_BYTES);
  cudaFuncSetAttribute(gemm2<1,false,false>, cudaFuncAttributeMaxDynamicSharedMemorySize, DSMEM_BYTES);
  cudaFuncSetAttribute(gemm2<0,true ,false>, cudaFuncAttributeMaxDynamicSharedMemorySize, DSMEM_BYTES);
  cudaFuncSetAttribute(gemm2<0,true ,true >, cudaFuncAttributeMaxDynamicSharedMemorySize, DSMEM_BYTES);
  cudaFuncSetAttribute(gemm2<2,false,false>, cudaFuncAttributeMaxDynamicSharedMemorySize, DSMEM_BYTES);

  const dim3 blk(256);

  // ---- precompute (tiny) ----
  build_wcat<<<16384, 256>>>(fwd_in_w, bwd_in_w, fwd_ln_g, bwd_ln_g);
  build_bcat<<<dim3(4096,2), 128>>>(fwd_in_w, bwd_in_w, fwd_ln_b, bwd_ln_b, fwd_in_b, bwd_in_b);
  build_wf1<<<8192, 256>>>(ffn1_w, ffn_ln_g);
  build_bf1<<<dim3(2048,2), 128>>>(ffn1_w, ffn_ln_b, ffn1_b);
  for (int i = 0; i < Lz; i++){
    // Wfo (1024x512) @ Mt -> wmid rows 0..1023  (grid: N/BN=2, M/BM=8)
    gemm2<0,false,false><<<dim3(2,8), blk, DSMEM_BYTES>>>(
        fwd_out_w + (size_t)i*1024*512, 512, 512,
        fwd_out_w, 512, 512,
        merge_w + (size_t)i*1024*512, 512, zb,
        nullptr, 0, nullptr,
        wmid + (size_t)i*2560*512, 512);
    // Wbo (1024x512) @ Mb -> wmid rows 1024..2047
    gemm2<0,false,false><<<dim3(2,8), blk, DSMEM_BYTES>>>(
        bwd_out_w + (size_t)i*1024*512, 512, 512,
        bwd_out_w, 512, 512,
        merge_w + (size_t)i*1024*512 + (size_t)512*512, 512, zb,
        nullptr, 0, nullptr,
        wmid + (size_t)i*2560*512 + (size_t)1024*512, 512);
  }
  build_wmid_sum<<<2048, 256>>>(merge_w);
  build_bmid<<<dim3(512,2), 128>>>(merge_w, merge_b, fwd_out_b, bwd_out_b);

  // ---- positional encoding path ----
  centroid_kernel<<<Mz, 256>>>(attn, cent, cent_out);
  enc_kernel<<<Mz, 256>>>(cent, enc);
  gemm2<1,false,false><<<dim3(2,128), blk, DSMEM_BYTES>>>(
      enc, 256, 256, enc, 256, 256, pm1_w, 512, pm1_b,
      nullptr, 0, nullptr, lnf, 512);
  gemm2<0,true,false><<<dim3(2,128), blk, DSMEM_BYTES>>>(
      lnf, 512, 512, lnf, 512, 512, pm2_w, 512, pm2_b,
      slots, 512, nullptr, xg, 512);

  // ---- layers ----
  for (int i = 0; i < Lz; i++){
    ln_plain_kernel<<<Mz, 128>>>(xg, lnf);
    // fused fwd+bwd in-proj with GLU epilogue  (N=4096: grid (16,128))
    gemm2<2,false,false><<<dim3(16,128), blk, DSMEM_BYTES>>>(
        lnf, 512, 512, lnf, 512, 512,
        wcat + (size_t)i*512*4096, 4096, bcat + (size_t)i*4096,
        nullptr, 0, nullptr, hh, 2048);
    // fused out-proj + merge + residual  (N=512: grid (2,128))
    gemm2<0,true,false><<<dim3(2,128), blk, DSMEM_BYTES>>>(
        hh, 2048, 2048, xg, 512, 2560,
        wmid + (size_t)i*2560*512, 512, bmid + (size_t)i*512,
        xg, 512, nullptr, res, 512);
    ln_chain2_kernel<<<Mz, 128>>>(res, norm_g + i*Dz, norm_b + i*Dz, xg, lnf);
    // ffn1 with gelu  (N=2048: grid (8,128))
    gemm2<1,false,false><<<dim3(8,128), blk, DSMEM_BYTES>>>(
        lnf, 512, 512, lnf, 512, 512,
        wf1 + (size_t)i*512*2048, 2048, bf1 + (size_t)i*2048,
        nullptr, 0, nullptr, hh, 2048);
    // ffn2 + residual + mask
    float* dst = (i == Lz-1) ? out : xg;
    gemm2<0,true,true><<<dim3(2,128), blk, DSMEM_BYTES>>>(
        hh, 2048, 2048, hh, 2048, 2048,
        ffn2_w + (size_t)i*2048*512, 512, ffn2_b + (size_t)i*512,
        xg, 512, keep, dst, 512);
  }
}

// round 11
// speedup vs baseline: 2.4822x; 2.4822x over previous
#include <cuda_runtime.h>
#include <cuda_bf16.h>
#include <math.h>
#include <cstdint>

// Problem constants
#define Bz   128
#define Kz   128
#define Dz   512
#define Lz   2
#define DIz  1024
#define Mz   (Bz*Kz)        // 16384 rows
#define HWz  4096

// GEMM tiling: CTA 128 threads, tile 128x128, 4 warps of 64x64 (2m x 2n), BK=32
// 3-stage cp.async pipeline, single __syncthreads per chunk.
#define BM 128
#define BN 128
#define BK 32
#define ASTR 36
#define BSTR 136
#define A_TILE_F (BM*ASTR)                      // 4608
#define B_TILE_F (BK*BSTR)                      // 4352
#define STAGE_F  (A_TILE_F + B_TILE_F)          // 8960
#define NSTAGE 3
#define DSMEM_BYTES (NSTAGE*STAGE_F*4)          // 107520 B  (x2 CTAs = 215KB <= 227KB)

// ---------------- scratch globals -------------------------------------------
__device__ float g_x   [Mz*Dz];
__device__ float g_lnf [Mz*Dz];
__device__ float g_h   [Mz*2048];       // GLU out / ffn1 out
__device__ float g_res [Mz*Dz];
__device__ float g_enc [Mz*256];
__device__ float g_cent[Mz*2];
// precomputed weights/biases
__device__ float g_wcat[2*512*4096];    // folded+permuted in-proj (z/gate interleaved)
__device__ float g_bcat[2*4096];
__device__ float g_wmid[2*2560*512];    // [WfoMt ; WboMb ; Mt+Mb]
__device__ float g_bmid[2*512];
__device__ float g_wf1 [2*512*2048];    // folded ffn1
__device__ float g_bf1 [2*2048];
__device__ float g_zero[512];           // zero bias (static zero-init)

// ---------------- helpers ---------------------------------------------------
__device__ __forceinline__ uint32_t smem_u32(const void* p){
  uint32_t a;
  asm("{ .reg .u64 t; cvta.to.shared.u64 t, %1; cvt.u32.u64 %0, t; }" : "=r"(a) : "l"(p));
  return a;
}
__device__ __forceinline__ void cpa16(void* dst, const void* src){
  asm volatile("cp.async.cg.shared.global [%0], [%1], 16;"
               :: "r"(smem_u32(dst)), "l"(src) : "memory");
}
__device__ __forceinline__ void cpa_commit(){
  asm volatile("cp.async.commit_group;" ::: "memory");
}
template<int N> __device__ __forceinline__ void cpa_wait(){
  asm volatile("cp.async.wait_group %0;" :: "n"(N) : "memory");
}
__device__ __forceinline__ void mma_tf32(float* d, const uint32_t* a, const uint32_t* b){
  asm volatile(
    "mma.sync.aligned.m16n8k8.row.col.f32.tf32.tf32.f32 "
    "{%0,%1,%2,%3}, {%4,%5,%6,%7}, {%8,%9}, {%0,%1,%2,%3};"
    : "+f"(d[0]), "+f"(d[1]), "+f"(d[2]), "+f"(d[3])
    : "r"(a[0]), "r"(a[1]), "r"(a[2]), "r"(a[3]), "r"(b[0]), "r"(b[1]));
}
__device__ __forceinline__ float tf32rna(float x){
  float r; asm("cvt.rna.tf32.f32 %0, %1;" : "=f"(r) : "f"(x)); return r;
}
__device__ __forceinline__ float gelu_exact(float x){
  return 0.5f * x * (1.0f + erff(x * 0.70710678118654752f));
}
__device__ __forceinline__ float sigmoidf(float x){
  return 1.0f / (1.0f + expf(-x));
}

// ---------------- tf32 mma GEMM: Out = act(Acat @ W + bias) [+Add][*mask] ----
// Acat = [A1 (K1 cols) | A2 (Ktot-K1 cols)], row-major with strides ld1/ld2.
// ACT: 0 none, 1 gelu, 2 GLU (silu(even)*sigmoid(odd) -> col ((n&2047)>>1)+(n>>11)*1024)
template<int ACT, bool HAS_ADD, bool HAS_MASK>
__global__ __launch_bounds__(128, 2) void gemm2(
    const float* __restrict__ A1, int ld1, int K1,
    const float* __restrict__ A2, int ld2, int Ktot,
    const float* __restrict__ W, int N,
    const float* __restrict__ bias,
    const float* __restrict__ Add, int ldadd,
    const float* __restrict__ mask,
    float* __restrict__ Out, int ldout)
{
  extern __shared__ float sm[];
  const int tid  = threadIdx.x;
  const int lane = tid & 31;
  const int warp = tid >> 5;
  const int wm   = warp & 1;          // row half (64)
  const int wn   = warp >> 1;         // col half (64)
  const int m0 = blockIdx.y * BM;
  const int n0 = blockIdx.x * BN;

  float acc[4][8][4];
#pragma unroll
  for (int i=0;i<4;i++)
#pragma unroll
    for (int j=0;j<8;j++)
#pragma unroll
      for (int r=0;r<4;r++) acc[i][j][r]=0.f;

  const int nch = Ktot / BK;

  auto load_chunk = [&](int c){
    const int k0 = c*BK;
    const float* src; int ld;
    if (k0 < K1){ src = A1 + (size_t)m0*ld1 + k0; ld = ld1; }
    else        { src = A2 + (size_t)m0*ld2 + (k0 - K1); ld = ld2; }
    float* sA = sm + (c % NSTAGE)*STAGE_F;
    float* sB = sA + A_TILE_F;
    const float* Wb = W + (size_t)k0*N + n0;
#pragma unroll
    for (int i=0;i<8;i++){                 // A: 128 rows x 32 floats = 1024 x 16B
      int idx = tid + i*128;
      int m  = idx >> 3;
      int k4 = idx & 7;
      cpa16(sA + m*ASTR + k4*4, src + (size_t)m*ld + k4*4);
    }
#pragma unroll
    for (int i=0;i<8;i++){                 // B: 32 rows x 128 floats = 1024 x 16B
      int idx = tid + i*128;
      int r  = idx >> 5;
      int c4 = idx & 31;
      cpa16(sB + r*BSTR + c4*4, Wb + (size_t)r*N + c4*4);
    }
    cpa_commit();
  };

  load_chunk(0);
  load_chunk(1);      // nch >= 8 always for our shapes

  for (int c = 0; c < nch; c++){
    cpa_wait<1>();    // chunk c has landed (FIFO; one group committed per iter)
    __syncthreads();  // all threads' chunk-c data visible + compute(c-1) finished

    // prefetch AFTER the barrier: writes buf (c+2)%3 == (c-1)%3,
    // whose readers (compute(c-1)) are provably done.
    if (c+2 < nch) load_chunk(c+2); else cpa_commit();

    const float* sA = sm + (c % NSTAGE)*STAGE_F;
    const float* sB = sA + A_TILE_F;

#pragma unroll
    for (int ks = 0; ks < BK/8; ks++){
      uint32_t afr[4][4];
#pragma unroll
      for (int mi=0;mi<4;mi++){
        int r  = wm*64 + mi*16 + (lane>>2);
        int cc = ks*8 + (lane&3);
        afr[mi][0] = __float_as_uint(sA[r*ASTR + cc]);
        afr[mi][1] = __float_as_uint(sA[(r+8)*ASTR + cc]);
        afr[mi][2] = __float_as_uint(sA[r*ASTR + cc + 4]);
        afr[mi][3] = __float_as_uint(sA[(r+8)*ASTR + cc + 4]);
      }
      uint32_t bfr[8][2];
#pragma unroll
      for (int nj=0;nj<8;nj++){
        int rr = ks*8 + (lane&3);
        int cc = wn*64 + nj*8 + (lane>>2);
        bfr[nj][0] = __float_as_uint(sB[rr*BSTR + cc]);
        bfr[nj][1] = __float_as_uint(sB[(rr+4)*BSTR + cc]);
      }
#pragma unroll
      for (int mi=0;mi<4;mi++)
#pragma unroll
        for (int nj=0;nj<8;nj++)
          mma_tf32(acc[mi][nj], afr[mi], bfr[nj]);
    }
    // no end-of-body barrier: next iteration's barrier provides the ordering
  }

  // ---- epilogue ----
#pragma unroll
  for (int mi=0;mi<4;mi++){
    const int r0 = m0 + wm*64 + mi*16 + (lane>>2);
    const int r1 = r0 + 8;
    const float mk0 = HAS_MASK ? mask[r0] : 1.f;
    const float mk1 = HAS_MASK ? mask[r1] : 1.f;
#pragma unroll
    for (int nj=0;nj<8;nj++){
      const int cb = n0 + wn*64 + nj*8 + (lane&3)*2;
      const float b0 = bias[cb], b1 = bias[cb+1];
      float v0 = acc[mi][nj][0] + b0;
      float v1 = acc[mi][nj][1] + b1;
      float v2 = acc[mi][nj][2] + b0;
      float v3 = acc[mi][nj][3] + b1;
      if (ACT == 2){
        const int oc = ((cb & 2047) >> 1) + (cb >> 11)*1024;
        Out[(size_t)r0*ldout + oc] = v0 * sigmoidf(v0) * sigmoidf(v1);
        Out[(size_t)r1*ldout + oc] = v2 * sigmoidf(v2) * sigmoidf(v3);
      } else {
        if (ACT == 1){
          v0 = gelu_exact(v0); v1 = gelu_exact(v1);
          v2 = gelu_exact(v2); v3 = gelu_exact(v3);
        }
        if (HAS_ADD){
          v0 += Add[(size_t)r0*ldadd + cb];   v1 += Add[(size_t)r0*ldadd + cb+1];
          v2 += Add[(size_t)r1*ldadd + cb];   v3 += Add[(size_t)r1*ldadd + cb+1];
        }
        if (HAS_MASK){ v0*=mk0; v1*=mk0; v2*=mk1; v3*=mk1; }
        *(float2*)&Out[(size_t)r0*ldout + cb] = make_float2(v0, v1);
        *(float2*)&Out[(size_t)r1*ldout + cb] = make_float2(v2, v3);
      }
    }
  }
}

// ---------------- LayerNorm kernels (D=512) ---------------------------------
__device__ __forceinline__ float block_sum_128(float v, volatile float* sh){
#pragma unroll
  for (int o=16;o>0;o>>=1) v += __shfl_xor_sync(0xffffffffu, v, o);
  int w = threadIdx.x >> 5;
  if ((threadIdx.x & 31)==0) sh[w] = v;
  __syncthreads();
  float r = sh[0]+sh[1]+sh[2]+sh[3];
  __syncthreads();
  return r;
}

__global__ __launch_bounds__(128) void ln_plain_kernel(
  const float* __restrict__ X, float* __restrict__ Y)
{
  __shared__ float sh[4];
  int row = blockIdx.x, t = threadIdx.x;
  float4 v = ((const float4*)(X + (size_t)row*Dz))[t];
  float s = block_sum_128(v.x+v.y+v.z+v.w, sh);
  float mean = s * (1.0f/Dz);
  float dx=v.x-mean, dy=v.y-mean, dz=v.z-mean, dw=v.w-mean;
  float sq = block_sum_128(dx*dx+dy*dy+dz*dz+dw*dw, sh);
  float inv = rsqrtf(sq*(1.0f/Dz) + 1e-5f);
  ((float4*)(Y + (size_t)row*Dz))[t] = make_float4(dx*inv, dy*inv, dz*inv, dw*inv);
}

__global__ __launch_bounds__(128) void ln_chain2_kernel(
  const float* __restrict__ X,
  const float* __restrict__ g, const float* __restrict__ b,
  float* __restrict__ Y1, float* __restrict__ Y2)
{
  __shared__ float sh[4];
  int row = blockIdx.x, t = threadIdx.x;
  float4 v = ((const float4*)(X + (size_t)row*Dz))[t];
  float s = block_sum_128(v.x+v.y+v.z+v.w, sh);
  float mean = s * (1.0f/Dz);
  float dx=v.x-mean, dy=v.y-mean, dz=v.z-mean, dw=v.w-mean;
  float sq = block_sum_128(dx*dx+dy*dy+dz*dz+dw*dw, sh);
  float inv = rsqrtf(sq*(1.0f/Dz) + 1e-5f);
  float4 G = ((const float4*)g)[t]; float4 Bb = ((const float4*)b)[t];
  float4 y = make_float4(dx*inv*G.x+Bb.x, dy*inv*G.y+Bb.y, dz*inv*G.z+Bb.z, dw*inv*G.w+Bb.w);
  ((float4*)(Y1 + (size_t)row*Dz))[t] = y;
  float s2 = block_sum_128(y.x+y.y+y.z+y.w, sh);
  float m2 = s2 * (1.0f/Dz);
  float ex=y.x-m2, ey=y.y-m2, ez=y.z-m2, ew=y.w-m2;
  float sq2 = block_sum_128(ex*ex+ey*ey+ez*ez+ew*ew, sh);
  float inv2 = rsqrtf(sq2*(1.0f/Dz) + 1e-5f);
  ((float4*)(Y2 + (size_t)row*Dz))[t] = make_float4(ex*inv2, ey*inv2, ez*inv2, ew*inv2);
}

// ---------------- centroids / enc -------------------------------------------
__global__ __launch_bounds__(256) void centroid_kernel(
  const float* __restrict__ attn, float* __restrict__ cent, float* __restrict__ cent_out)
{
  int bk = blockIdx.x;
  const float* a = attn + (size_t)bk*HWz;
  float s=0.f, sx=0.f, sy=0.f;
#pragma unroll 4
  for (int i=threadIdx.x; i<HWz; i+=256){
    float v = a[i];
    s  += v;
    sx += v * (float)(i & 63);
    sy += v * (float)(i >> 6);
  }
#pragma unroll
  for (int o=16;o>0;o>>=1){
    s  += __shfl_xor_sync(0xffffffffu, s,  o);
    sx += __shfl_xor_sync(0xffffffffu, sx, o);
    sy += __shfl_xor_sync(0xffffffffu, sy, o);
  }
  __shared__ float sh[24];
  int w = threadIdx.x >> 5;
  if ((threadIdx.x & 31)==0){ sh[w]=s; sh[8+w]=sx; sh[16+w]=sy; }
  __syncthreads();
  if (threadIdx.x==0){
    float S=0.f, SX=0.f, SY=0.f;
    for (int i=0;i<8;i++){ S+=sh[i]; SX+=sh[8+i]; SY+=sh[16+i]; }
    float invs = 1.0f/(S + 1e-8f);
    float cx = SX * (1.0f/63.0f) * invs;
    float cy = SY * (1.0f/63.0f) * invs;
    cent[bk*2]   = cx;
    cent[bk*2+1] = cy;
    if (cent_out){ cent_out[bk*2] = cx; cent_out[bk*2+1] = cy; }
  }
}

__global__ __launch_bounds__(256) void enc_kernel(
  const float* __restrict__ cent, float* __restrict__ E)
{
  int row = blockIdx.x, j = threadIdx.x;
  int f  = j >> 6;
  int jj = j & 63;
  int fi = jj & 31;
  float feat;
  if      (f==0) feat = cent[row*2];
  else if (f==1) feat = cent[row*2+1];
  else           feat = 0.1f;
  float freq = expf(-(float)fi * 0.28782313662425575f);
  float ang = feat * freq * 3.14159f;
  E[(size_t)row*256 + j] = (jj < 32) ? sinf(ang) : cosf(ang);
}

// ---------------- weight precompute kernels ---------------------------------
__global__ __launch_bounds__(256) void build_wcat(
  const float* __restrict__ fw, const float* __restrict__ bw,
  const float* __restrict__ fg, const float* __restrict__ bg)
{
  size_t idx = (size_t)blockIdx.x*256 + threadIdx.x;   // 2*512*4096
  int n = idx & 4095;
  int k = (idx >> 12) & 511;
  int i = (int)(idx >> 21);
  int br = n >> 11;
  int j2 = n & 2047;
  int src = (j2 & 1) ? 1024 + (j2 >> 1) : (j2 >> 1);
  const float* W = (br ? bw : fw) + (size_t)i*512*2048;
  const float* G = (br ? bg : fg) + i*512;
  g_wcat[idx] = tf32rna(G[k] * W[(size_t)k*2048 + src]);
}

__global__ __launch_bounds__(128) void build_bcat(
  const float* __restrict__ fw, const float* __restrict__ bw,
  const float* __restrict__ fb, const float* __restrict__ bb,     // ln betas
  const float* __restrict__ fib, const float* __restrict__ bib)   // in biases
{
  int n = blockIdx.x;          // 0..4095
  int i = blockIdx.y;          // layer
  int br = n >> 11;
  int j2 = n & 2047;
  int src = (j2 & 1) ? 1024 + (j2 >> 1) : (j2 >> 1);
  const float* W   = (br ? bw : fw) + (size_t)i*512*2048;
  const float* LNB = (br ? bb : fb) + i*512;
  const float* INB = (br ? bib : fib) + i*2048;
  __shared__ float sh[4];
  float p = 0.f;
  for (int k = threadIdx.x; k < 512; k += 128)
    p += LNB[k] * W[(size_t)k*2048 + src];
  float tot = block_sum_128(p, sh);
  if (threadIdx.x == 0) g_bcat[i*4096 + n] = tot + INB[src];
}

__global__ __launch_bounds__(256) void build_wf1(
  const float* __restrict__ w1, const float* __restrict__ g)
{
  size_t idx = (size_t)blockIdx.x*256 + threadIdx.x;   // 2*512*2048
  int k = (int)((idx >> 11) & 511);
  int i = (int)(idx >> 20);
  g_wf1[idx] = tf32rna(g[i*512 + k] * w1[idx]);
}

__global__ __launch_bounds__(128) void build_bf1(
  const float* __restrict__ w1, const float* __restrict__ lnb,
  const float* __restrict__ b1)
{
  int n = blockIdx.x;          // 0..2047
  int i = blockIdx.y;
  const float* W = w1 + (size_t)i*512*2048;
  __shared__ float sh[4];
  float p = 0.f;
  for (int k = threadIdx.x; k < 512; k += 128)
    p += lnb[i*512 + k] * W[(size_t)k*2048 + n];
  float tot = block_sum_128(p, sh);
  if (threadIdx.x == 0) g_bf1[i*2048 + n] = tot + b1[i*2048 + n];
}

__global__ __launch_bounds__(256) void build_wmid_sum(const float* __restrict__ mw)
{
  size_t idx = (size_t)blockIdx.x*256 + threadIdx.x;   // 2*512*512
  int c = idx & 511;
  int k = (int)((idx >> 9) & 511);
  int i = (int)(idx >> 18);
  const float* Mt = mw + (size_t)i*1024*512;
  g_wmid[(size_t)i*2560*512 + (size_t)(2048 + k)*512 + c] =
      tf32rna(Mt[(size_t)k*512 + c] + Mt[(size_t)(512 + k)*512 + c]);
}

__global__ __launch_bounds__(128) void build_bmid(
  const float* __restrict__ mw, const float* __restrict__ mb,
  const float* __restrict__ fob, const float* __restrict__ bob)
{
  int c = blockIdx.x;          // 0..511
  int i = blockIdx.y;
  const float* Mt = mw + (size_t)i*1024*512;
  __shared__ float sh[4];
  float p = 0.f;
  for (int k = threadIdx.x; k < 512; k += 128){
    p += fob[i*512 + k] * Mt[(size_t)k*512 + c];
    p += bob[i*512 + k] * Mt[(size_t)(512 + k)*512 + c];
  }
  float tot = block_sum_128(p, sh);
  if (threadIdx.x == 0) g_bmid[i*512 + c] = tot + mb[i*512 + c];
}

// ---------------- host orchestration ----------------------------------------
extern "C" void kernel_launch(void* const* d_in, const int* in_sizes, int n_in,
                              void* d_out, int out_size)
{
  const float* slots     = (const float*)d_in[0];
  const float* keep      = (const float*)d_in[1];
  const float* attn      = (const float*)d_in[2];
  const float* pm1_w     = (const float*)d_in[5];
  const float* pm1_b     = (const float*)d_in[6];
  const float* pm2_w     = (const float*)d_in[7];
  const float* pm2_b     = (const float*)d_in[8];
  const float* fwd_ln_g  = (const float*)d_in[9];
  const float* fwd_ln_b  = (const float*)d_in[10];
  const float* fwd_in_w  = (const float*)d_in[11];
  const float* fwd_in_b  = (const float*)d_in[12];
  const float* fwd_out_w = (const float*)d_in[13];
  const float* fwd_out_b = (const float*)d_in[14];
  const float* bwd_ln_g  = (const float*)d_in[15];
  const float* bwd_ln_b  = (const float*)d_in[16];
  const float* bwd_in_w  = (const float*)d_in[17];
  const float* bwd_in_b  = (const float*)d_in[18];
  const float* bwd_out_w = (const float*)d_in[19];
  const float* bwd_out_b = (const float*)d_in[20];
  const float* merge_w   = (const float*)d_in[21];
  const float* merge_b   = (const float*)d_in[22];
  const float* norm_g    = (const float*)d_in[23];
  const float* norm_b    = (const float*)d_in[24];
  const float* ffn_ln_g  = (const float*)d_in[25];
  const float* ffn_ln_b  = (const float*)d_in[26];
  const float* ffn1_w    = (const float*)d_in[27];
  const float* ffn1_b    = (const float*)d_in[28];
  const float* ffn2_w    = (const float*)d_in[29];
  const float* ffn2_b    = (const float*)d_in[30];
  float* out = (float*)d_out;

  float *xg, *lnf, *hh, *res, *enc, *cent, *wcat, *bcat, *wmid, *bmid, *wf1, *bf1, *zb;
  cudaGetSymbolAddress((void**)&xg,   g_x);
  cudaGetSymbolAddress((void**)&lnf,  g_lnf);
  cudaGetSymbolAddress((void**)&hh,   g_h);
  cudaGetSymbolAddress((void**)&res,  g_res);
  cudaGetSymbolAddress((void**)&enc,  g_enc);
  cudaGetSymbolAddress((void**)&cent, g_cent);
  cudaGetSymbolAddress((void**)&wcat, g_wcat);
  cudaGetSymbolAddress((void**)&bcat, g_bcat);
  cudaGetSymbolAddress((void**)&wmid, g_wmid);
  cudaGetSymbolAddress((void**)&bmid, g_bmid);
  cudaGetSymbolAddress((void**)&wf1,  g_wf1);
  cudaGetSymbolAddress((void**)&bf1,  g_bf1);
  cudaGetSymbolAddress((void**)&zb,   g_zero);

  float* cent_out = nullptr;
  if ((long long)out_size >= (long long)Mz*Dz + (long long)Mz*2)
    cent_out = out + (size_t)Mz*Dz;

  cudaFuncSetAttribute(gemm2<0,false,false>, cudaFuncAttributeMaxDynamicSharedMemorySize, DSMEM_BYTES);
  cudaFuncSetAttribute(gemm2<1,false,false>, cudaFuncAttributeMaxDynamicSharedMemorySize, DSMEM_BYTES);
  cudaFuncSetAttribute(gemm2<0,true ,false>, cudaFuncAttributeMaxDynamicSharedMemorySize, DSMEM_BYTES);
  cudaFuncSetAttribute(gemm2<0,true ,true >, cudaFuncAttributeMaxDynamicSharedMemorySize, DSMEM_BYTES);
  cudaFuncSetAttribute(gemm2<2,false,false>, cudaFuncAttributeMaxDynamicSharedMemorySize, DSMEM_BYTES);

  const dim3 blk(128);

  // ---- precompute (tiny) ----
  build_wcat<<<16384, 256>>>(fwd_in_w, bwd_in_w, fwd_ln_g, bwd_ln_g);
  build_bcat<<<dim3(4096,2), 128>>>(fwd_in_w, bwd_in_w, fwd_ln_b, bwd_ln_b, fwd_in_b, bwd_in_b);
  build_wf1<<<8192, 256>>>(ffn1_w, ffn_ln_g);
  build_bf1<<<dim3(2048,2), 128>>>(ffn1_w, ffn_ln_b, ffn1_b);
  for (int i = 0; i < Lz; i++){
    // Wfo (1024x512) @ Mt -> wmid rows 0..1023
    gemm2<0,false,false><<<dim3(4,8), blk, DSMEM_BYTES>>>(
        fwd_out_w + (size_t)i*1024*512, 512, 512,
        fwd_out_w, 512, 512,
        merge_w + (size_t)i*1024*512, 512, zb,
        nullptr, 0, nullptr,
        wmid + (size_t)i*2560*512, 512);
    // Wbo (1024x512) @ Mb -> wmid rows 1024..2047
    gemm2<0,false,false><<<dim3(4,8), blk, DSMEM_BYTES>>>(
        bwd_out_w + (size_t)i*1024*512, 512, 512,
        bwd_out_w, 512, 512,
        merge_w + (size_t)i*1024*512 + (size_t)512*512, 512, zb,
        nullptr, 0, nullptr,
        wmid + (size_t)i*2560*512 + (size_t)1024*512, 512);
  }
  build_wmid_sum<<<2048, 256>>>(merge_w);
  build_bmid<<<dim3(512,2), 128>>>(merge_w, merge_b, fwd_out_b, bwd_out_b);

  // ---- positional encoding path ----
  centroid_kernel<<<Mz, 256>>>(attn, cent, cent_out);
  enc_kernel<<<Mz, 256>>>(cent, enc);
  gemm2<1,false,false><<<dim3(4,128), blk, DSMEM_BYTES>>>(
      enc, 256, 256, enc, 256, 256, pm1_w, 512, pm1_b,
      nullptr, 0, nullptr, lnf, 512);
  gemm2<0,true,false><<<dim3(4,128), blk, DSMEM_BYTES>>>(
      lnf, 512, 512, lnf, 512, 512, pm2_w, 512, pm2_b,
      slots, 512, nullptr, xg, 512);

  // ---- layers ----
  for (int i = 0; i < Lz; i++){
    ln_plain_kernel<<<Mz, 128>>>(xg, lnf);
    // fused fwd+bwd in-proj with GLU epilogue  (N=4096: grid (32,128))
    gemm2<2,false,false><<<dim3(32,128), blk, DSMEM_BYTES>>>(
        lnf, 512, 512, lnf, 512, 512,
        wcat + (size_t)i*512*4096, 4096, bcat + (size_t)i*4096,
        nullptr, 0, nullptr, hh, 2048);
    // fused out-proj + merge + residual  (N=512: grid (4,128))
    gemm2<0,true,false><<<dim3(4,128), blk, DSMEM_BYTES>>>(
        hh, 2048, 2048, xg, 512, 2560,
        wmid + (size_t)i*2560*512, 512, bmid + (size_t)i*512,
        xg, 512, nullptr, res, 512);
    ln_chain2_kernel<<<Mz, 128>>>(res, norm_g + i*Dz, norm_b + i*Dz, xg, lnf);
    // ffn1 with gelu  (N=2048: grid (16,128))
    gemm2<1,false,false><<<dim3(16,128), blk, DSMEM_BYTES>>>(
        lnf, 512, 512, lnf, 512, 512,
        wf1 + (size_t)i*512*2048, 2048, bf1 + (size_t)i*2048,
        nullptr, 0, nullptr, hh, 2048);
    // ffn2 + residual + mask
    float* dst = (i == Lz-1) ? out : xg;
    gemm2<0,true,true><<<dim3(4,128), blk, DSMEM_BYTES>>>(
        hh, 2048, 2048, hh, 2048, 2048,
        ffn2_w + (size_t)i*2048*512, 512, ffn2_b + (size_t)i*512,
        xg, 512, keep, dst, 512);
  }
}

// round 13
// speedup vs baseline: 3.5567x; 1.4329x over previous
#include <cuda_runtime.h>
#include <cuda_fp16.h>
#include <math.h>
#include <cstdint>

// Problem constants
#define Bz   128
#define Kz   128
#define Dz   512
#define Lz   2
#define Mz   (Bz*Kz)        // 16384 rows
#define HWz  4096

// fp16 GEMM tiling: CTA 128 threads, tile 128x128, 4 warps of 64x64 (2m x 2n), BK=32
#define BM 128
#define BN 128
#define BK 32
#define ASTRh 40                      // A smem row stride in halves (32 + 8 pad)
#define BSTRh 136                     // B smem row stride in halves (128 + 8 pad)
#define A_TILE_H (BM*ASTRh)           // 5120 halves
#define B_TILE_H (BK*BSTRh)           // 4352 halves
#define STAGE_H  (A_TILE_H + B_TILE_H)// 9472 halves
#define DSMEM_BYTES (2*STAGE_H*2)     // 37888 B (< 48KB default; 2 CTAs/SM)

// ---------------- scratch globals -------------------------------------------
__device__ float  g_x   [Mz*Dz];      // fp32 state
__device__ float  g_res [Mz*Dz];
__device__ float  g_cent[Mz*2];
__device__ __half g_enc_h[Mz*256];
__device__ __half g_lnf_h[Mz*Dz];
__device__ __half g_x_h [Mz*Dz];
__device__ __half g_h_h [Mz*2048];
__device__ __half g_wcat_h[2*512*4096];
__device__ __half g_wf1_h [2*512*2048];
__device__ __half g_wmid_h[2*2560*512];
__device__ __half g_ffn2_h[2*2048*512];
__device__ __half g_pm1_h [256*512];
__device__ __half g_pm2_h [512*512];
__device__ __half g_fow_h [2*1024*512];
__device__ __half g_bow_h [2*1024*512];
__device__ __half g_mrg_h [2*1024*512];
__device__ float  g_bcat[2*4096];
__device__ float  g_bmid[2*512];
__device__ float  g_bf1 [2*2048];
__device__ float  g_zero[512];

// ---------------- helpers ---------------------------------------------------
__device__ __forceinline__ uint32_t smem_u32(const void* p){
  uint32_t a;
  asm("{ .reg .u64 t; cvta.to.shared.u64 t, %1; cvt.u32.u64 %0, t; }" : "=r"(a) : "l"(p));
  return a;
}
__device__ __forceinline__ void cpa16(void* dst, const void* src){
  asm volatile("cp.async.cg.shared.global [%0], [%1], 16;"
               :: "r"(smem_u32(dst)), "l"(src) : "memory");
}
__device__ __forceinline__ void cpa_commit(){
  asm volatile("cp.async.commit_group;" ::: "memory");
}
template<int N> __device__ __forceinline__ void cpa_wait(){
  asm volatile("cp.async.wait_group %0;" :: "n"(N) : "memory");
}
__device__ __forceinline__ void mma_f16(float* d, const uint32_t* a, const uint32_t* b){
  asm volatile(
    "mma.sync.aligned.m16n8k16.row.col.f32.f16.f16.f32 "
    "{%0,%1,%2,%3}, {%4,%5,%6,%7}, {%8,%9}, {%0,%1,%2,%3};"
    : "+f"(d[0]), "+f"(d[1]), "+f"(d[2]), "+f"(d[3])
    : "r"(a[0]), "r"(a[1]), "r"(a[2]), "r"(a[3]), "r"(b[0]), "r"(b[1]));
}
__device__ __forceinline__ float gelu_exact(float x){
  return 0.5f * x * (1.0f + erff(x * 0.70710678118654752f));
}
__device__ __forceinline__ float sigmoidf(float x){
  return 1.0f / (1.0f + expf(-x));
}

// ---------------- fp16 mma GEMM ----------------------------------------------
// Out(f32)/Outh(f16) = act(Acat @ W + bias) [+Add] [*mask]
// Acat = [A1 (K1 cols) | A2 (Ktot-K1 cols)] fp16 row-major; W fp16 [K][N] row-major.
// ACT: 0 none, 1 gelu, 2 GLU (silu(even)*sigmoid(odd) -> Outh col ((n&2047)>>1)+(n>>11)*1024)
template<int ACT, bool HAS_ADD, bool HAS_MASK>
__global__ __launch_bounds__(128, 2) void gemm_h(
    const __half* __restrict__ A1, int ld1, int K1,
    const __half* __restrict__ A2, int ld2, int Ktot,
    const __half* __restrict__ W, int N,
    const float* __restrict__ bias,
    const float* __restrict__ Add, int ldadd,
    const float* __restrict__ mask,
    float* __restrict__ Out, __half* __restrict__ Outh, int ldout)
{
  extern __shared__ __half smh[];
  const int tid  = threadIdx.x;
  const int lane = tid & 31;
  const int warp = tid >> 5;
  const int wm   = warp & 1;          // row half (64)
  const int wn   = warp >> 1;         // col half (64)
  const int m0 = blockIdx.y * BM;
  const int n0 = blockIdx.x * BN;

  float acc[4][8][4];
#pragma unroll
  for (int i=0;i<4;i++)
#pragma unroll
    for (int j=0;j<8;j++)
#pragma unroll
      for (int r=0;r<4;r++) acc[i][j][r]=0.f;

  const int nch = Ktot / BK;

  auto load_chunk = [&](int c, int buf){
    const int k0 = c*BK;
    const __half* src; int ld;
    if (k0 < K1){ src = A1 + (size_t)m0*ld1 + k0; ld = ld1; }
    else        { src = A2 + (size_t)m0*ld2 + (k0 - K1); ld = ld2; }
    __half* sA = smh + buf*STAGE_H;
    __half* sB = sA + A_TILE_H;
    const __half* Wb = W + (size_t)k0*N + n0;
    // A tile: 128 rows x 32 halves = 4096 halves = 512 x 16B
#pragma unroll
    for (int i=0;i<4;i++){
      int idx = tid + i*128;
      int m  = idx >> 2;
      int k8 = idx & 3;
      cpa16(sA + m*ASTRh + k8*8, src + (size_t)m*ld + k8*8);
    }
    // B tile: 32 k-rows x 128 halves = 4096 halves = 512 x 16B
#pragma unroll
    for (int i=0;i<4;i++){
      int idx = tid + i*128;
      int r   = idx >> 4;
      int c16 = idx & 15;
      cpa16(sB + r*BSTRh + c16*8, Wb + (size_t)r*N + c16*8);
    }
    cpa_commit();
  };

  load_chunk(0, 0);

  for (int c = 0; c < nch; c++){
    const int buf = c & 1;
    if (c+1 < nch){ load_chunk(c+1, (c+1)&1); cpa_wait<1>(); }
    else          { cpa_wait<0>(); }
    __syncthreads();

    const __half* sA = smh + buf*STAGE_H;
    const __half* sB = sA + A_TILE_H;

#pragma unroll
    for (int ks = 0; ks < 2; ks++){           // 2 x k16 per BK=32 chunk
      const int kb = ks*16;
      // A fragments: m16n8k16 layout, k-pairs contiguous -> LDS.32 of __half2
      uint32_t afr[4][4];
#pragma unroll
      for (int mi=0;mi<4;mi++){
        const int row = wm*64 + mi*16 + (lane>>2);
        const int kk  = kb + (lane&3)*2;
        afr[mi][0] = *(const uint32_t*)&sA[ row     *ASTRh + kk    ];
        afr[mi][1] = *(const uint32_t*)&sA[(row + 8)*ASTRh + kk    ];
        afr[mi][2] = *(const uint32_t*)&sA[ row     *ASTRh + kk + 8];
        afr[mi][3] = *(const uint32_t*)&sA[(row + 8)*ASTRh + kk + 8];
      }
      // B fragments: b0 = {B[k][n], B[k+1][n]}, b1 same at k+8
      uint32_t bfr[8][2];
      {
        const int kbb = kb + (lane&3)*2;
#pragma unroll
        for (int nj=0;nj<8;nj++){
          const int n = wn*64 + nj*8 + (lane>>2);
          __half2 h0 = __halves2half2(sB[(size_t)(kbb  )*BSTRh + n],
                                      sB[(size_t)(kbb+1)*BSTRh + n]);
          __half2 h1 = __halves2half2(sB[(size_t)(kbb+8)*BSTRh + n],
                                      sB[(size_t)(kbb+9)*BSTRh + n]);
          bfr[nj][0] = *(uint32_t*)&h0;
          bfr[nj][1] = *(uint32_t*)&h1;
        }
      }
#pragma unroll
      for (int mi=0;mi<4;mi++)
#pragma unroll
        for (int nj=0;nj<8;nj++)
          mma_f16(acc[mi][nj], afr[mi], bfr[nj]);
    }
    __syncthreads();
  }

  // ---- epilogue (C frag layout identical to tf32 path) ----
#pragma unroll
  for (int mi=0;mi<4;mi++){
    const int r0 = m0 + wm*64 + mi*16 + (lane>>2);
    const int r1 = r0 + 8;
    const float mk0 = HAS_MASK ? mask[r0] : 1.f;
    const float mk1 = HAS_MASK ? mask[r1] : 1.f;
#pragma unroll
    for (int nj=0;nj<8;nj++){
      const int cb = n0 + wn*64 + nj*8 + (lane&3)*2;
      const float b0 = bias[cb], b1 = bias[cb+1];
      float v0 = acc[mi][nj][0] + b0;
      float v1 = acc[mi][nj][1] + b1;
      float v2 = acc[mi][nj][2] + b0;
      float v3 = acc[mi][nj][3] + b1;
      if (ACT == 2){
        const int oc = ((cb & 2047) >> 1) + (cb >> 11)*1024;
        Outh[(size_t)r0*ldout + oc] = __float2half(v0 * sigmoidf(v0) * sigmoidf(v1));
        Outh[(size_t)r1*ldout + oc] = __float2half(v2 * sigmoidf(v2) * sigmoidf(v3));
      } else {
        if (ACT == 1){
          v0 = gelu_exact(v0); v1 = gelu_exact(v1);
          v2 = gelu_exact(v2); v3 = gelu_exact(v3);
        }
        if (HAS_ADD){
          v0 += Add[(size_t)r0*ldadd + cb];   v1 += Add[(size_t)r0*ldadd + cb+1];
          v2 += Add[(size_t)r1*ldadd + cb];   v3 += Add[(size_t)r1*ldadd + cb+1];
        }
        if (HAS_MASK){ v0*=mk0; v1*=mk0; v2*=mk1; v3*=mk1; }
        if (Out){
          *(float2*)&Out[(size_t)r0*ldout + cb] = make_float2(v0, v1);
          *(float2*)&Out[(size_t)r1*ldout + cb] = make_float2(v2, v3);
        }
        if (Outh){
          *(__half2*)&Outh[(size_t)r0*ldout + cb] = __floats2half2_rn(v0, v1);
          *(__half2*)&Outh[(size_t)r1*ldout + cb] = __floats2half2_rn(v2, v3);
        }
      }
    }
  }
}

// ---------------- LayerNorm kernels (D=512) ---------------------------------
__device__ __forceinline__ float block_sum_128(float v, volatile float* sh){
#pragma unroll
  for (int o=16;o>0;o>>=1) v += __shfl_xor_sync(0xffffffffu, v, o);
  int w = threadIdx.x >> 5;
  if ((threadIdx.x & 31)==0) sh[w] = v;
  __syncthreads();
  float r = sh[0]+sh[1]+sh[2]+sh[3];
  __syncthreads();
  return r;
}

__global__ __launch_bounds__(128) void ln_plain_h(
  const float* __restrict__ X, __half* __restrict__ Yh)
{
  __shared__ float sh[4];
  int row = blockIdx.x, t = threadIdx.x;
  float4 v = ((const float4*)(X + (size_t)row*Dz))[t];
  float s = block_sum_128(v.x+v.y+v.z+v.w, sh);
  float mean = s * (1.0f/Dz);
  float dx=v.x-mean, dy=v.y-mean, dz=v.z-mean, dw=v.w-mean;
  float sq = block_sum_128(dx*dx+dy*dy+dz*dz+dw*dw, sh);
  float inv = rsqrtf(sq*(1.0f/Dz) + 1e-5f);
  __half2* o = (__half2*)(Yh + (size_t)row*Dz);
  o[2*t]   = __floats2half2_rn(dx*inv, dy*inv);
  o[2*t+1] = __floats2half2_rn(dz*inv, dw*inv);
}

__global__ __launch_bounds__(128) void ln_chain2_h(
  const float* __restrict__ X,
  const float* __restrict__ g, const float* __restrict__ b,
  float* __restrict__ Y1f, __half* __restrict__ Y1h, __half* __restrict__ Y2h)
{
  __shared__ float sh[4];
  int row = blockIdx.x, t = threadIdx.x;
  float4 v = ((const float4*)(X + (size_t)row*Dz))[t];
  float s = block_sum_128(v.x+v.y+v.z+v.w, sh);
  float mean = s * (1.0f/Dz);
  float dx=v.x-mean, dy=v.y-mean, dz=v.z-mean, dw=v.w-mean;
  float sq = block_sum_128(dx*dx+dy*dy+dz*dz+dw*dw, sh);
  float inv = rsqrtf(sq*(1.0f/Dz) + 1e-5f);
  float4 G = ((const float4*)g)[t]; float4 Bb = ((const float4*)b)[t];
  float4 y = make_float4(dx*inv*G.x+Bb.x, dy*inv*G.y+Bb.y, dz*inv*G.z+Bb.z, dw*inv*G.w+Bb.w);
  ((float4*)(Y1f + (size_t)row*Dz))[t] = y;
  { __half2* o = (__half2*)(Y1h + (size_t)row*Dz);
    o[2*t] = __floats2half2_rn(y.x, y.y); o[2*t+1] = __floats2half2_rn(y.z, y.w); }
  float s2 = block_sum_128(y.x+y.y+y.z+y.w, sh);
  float m2 = s2 * (1.0f/Dz);
  float ex=y.x-m2, ey=y.y-m2, ez=y.z-m2, ew=y.w-m2;
  float sq2 = block_sum_128(ex*ex+ey*ey+ez*ez+ew*ew, sh);
  float inv2 = rsqrtf(sq2*(1.0f/Dz) + 1e-5f);
  __half2* o2 = (__half2*)(Y2h + (size_t)row*Dz);
  o2[2*t]   = __floats2half2_rn(ex*inv2, ey*inv2);
  o2[2*t+1] = __floats2half2_rn(ez*inv2, ew*inv2);
}

// ---------------- centroids / enc -------------------------------------------
__global__ __launch_bounds__(256) void centroid_kernel(
  const float* __restrict__ attn, float* __restrict__ cent, float* __restrict__ cent_out)
{
  int bk = blockIdx.x;
  const float* a = attn + (size_t)bk*HWz;
  float s=0.f, sx=0.f, sy=0.f;
#pragma unroll 4
  for (int i=threadIdx.x; i<HWz; i+=256){
    float v = a[i];
    s  += v;
    sx += v * (float)(i & 63);
    sy += v * (float)(i >> 6);
  }
#pragma unroll
  for (int o=16;o>0;o>>=1){
    s  += __shfl_xor_sync(0xffffffffu, s,  o);
    sx += __shfl_xor_sync(0xffffffffu, sx, o);
    sy += __shfl_xor_sync(0xffffffffu, sy, o);
  }
  __shared__ float sh[24];
  int w = threadIdx.x >> 5;
  if ((threadIdx.x & 31)==0){ sh[w]=s; sh[8+w]=sx; sh[16+w]=sy; }
  __syncthreads();
  if (threadIdx.x==0){
    float S=0.f, SX=0.f, SY=0.f;
    for (int i=0;i<8;i++){ S+=sh[i]; SX+=sh[8+i]; SY+=sh[16+i]; }
    float invs = 1.0f/(S + 1e-8f);
    float cx = SX * (1.0f/63.0f) * invs;
    float cy = SY * (1.0f/63.0f) * invs;
    cent[bk*2]   = cx;
    cent[bk*2+1] = cy;
    if (cent_out){ cent_out[bk*2] = cx; cent_out[bk*2+1] = cy; }
  }
}

__global__ __launch_bounds__(256) void enc_kernel_h(
  const float* __restrict__ cent, __half* __restrict__ E)
{
  int row = blockIdx.x, j = threadIdx.x;
  int f  = j >> 6;
  int jj = j & 63;
  int fi = jj & 31;
  float feat;
  if      (f==0) feat = cent[row*2];
  else if (f==1) feat = cent[row*2+1];
  else           feat = 0.1f;
  float freq = expf(-(float)fi * 0.28782313662425575f);
  float ang = feat * freq * 3.14159f;
  E[(size_t)row*256 + j] = __float2half((jj < 32) ? sinf(ang) : cosf(ang));
}

// ---------------- weight precompute -----------------------------------------
__global__ __launch_bounds__(256) void f2h_kernel(
  const float* __restrict__ src, __half* __restrict__ dst, int n)
{
  int i = blockIdx.x*256 + threadIdx.x;
  if (i < n) dst[i] = __float2half(src[i]);
}

__global__ __launch_bounds__(256) void build_wcat(
  const float* __restrict__ fw, const float* __restrict__ bw,
  const float* __restrict__ fg, const float* __restrict__ bg)
{
  size_t idx = (size_t)blockIdx.x*256 + threadIdx.x;   // 2*512*4096
  int n = idx & 4095;
  int k = (idx >> 12) & 511;
  int i = (int)(idx >> 21);
  int br = n >> 11;
  int j2 = n & 2047;
  int src = (j2 & 1) ? 1024 + (j2 >> 1) : (j2 >> 1);
  const float* W = (br ? bw : fw) + (size_t)i*512*2048;
  const float* G = (br ? bg : fg) + i*512;
  g_wcat_h[idx] = __float2half(G[k] * W[(size_t)k*2048 + src]);
}

__global__ __launch_bounds__(128) void build_bcat(
  const float* __restrict__ fw, const float* __restrict__ bw,
  const float* __restrict__ fb, const float* __restrict__ bb,
  const float* __restrict__ fib, const float* __restrict__ bib)
{
  int n = blockIdx.x;          // 0..4095
  int i = blockIdx.y;
  int br = n >> 11;
  int j2 = n & 2047;
  int src = (j2 & 1) ? 1024 + (j2 >> 1) : (j2 >> 1);
  const float* W   = (br ? bw : fw) + (size_t)i*512*2048;
  const float* LNB = (br ? bb : fb) + i*512;
  const float* INB = (br ? bib : fib) + i*2048;
  __shared__ float sh[4];
  float p = 0.f;
  for (int k = threadIdx.x; k < 512; k += 128)
    p += LNB[k] * W[(size_t)k*2048 + src];
  float tot = block_sum_128(p, sh);
  if (threadIdx.x == 0) g_bcat[i*4096 + n] = tot + INB[src];
}

__global__ __launch_bounds__(256) void build_wf1(
  const float* __restrict__ w1, const float* __restrict__ g)
{
  size_t idx = (size_t)blockIdx.x*256 + threadIdx.x;   // 2*512*2048
  int k = (int)((idx >> 11) & 511);
  int i = (int)(idx >> 20);
  g_wf1_h[idx] = __float2half(g[i*512 + k] * w1[idx]);
}

__global__ __launch_bounds__(128) void build_bf1(
  const float* __restrict__ w1, const float* __restrict__ lnb,
  const float* __restrict__ b1)
{
  int n = blockIdx.x;          // 0..2047
  int i = blockIdx.y;
  const float* W = w1 + (size_t)i*512*2048;
  __shared__ float sh[4];
  float p = 0.f;
  for (int k = threadIdx.x; k < 512; k += 128)
    p += lnb[i*512 + k] * W[(size_t)k*2048 + n];
  float tot = block_sum_128(p, sh);
  if (threadIdx.x == 0) g_bf1[i*2048 + n] = tot + b1[i*2048 + n];
}

__global__ __launch_bounds__(256) void build_wmid_sum(const float* __restrict__ mw)
{
  size_t idx = (size_t)blockIdx.x*256 + threadIdx.x;   // 2*512*512
  int c = idx & 511;
  int k = (int)((idx >> 9) & 511);
  int i = (int)(idx >> 18);
  const float* Mt = mw + (size_t)i*1024*512;
  g_wmid_h[(size_t)i*2560*512 + (size_t)(2048 + k)*512 + c] =
      __float2half(Mt[(size_t)k*512 + c] + Mt[(size_t)(512 + k)*512 + c]);
}

__global__ __launch_bounds__(128) void build_bmid(
  const float* __restrict__ mw, const float* __restrict__ mb,
  const float* __restrict__ fob, const float* __restrict__ bob)
{
  int c = blockIdx.x;          // 0..511
  int i = blockIdx.y;
  const float* Mt = mw + (size_t)i*1024*512;
  __shared__ float sh[4];
  float p = 0.f;
  for (int k = threadIdx.x; k < 512; k += 128){
    p += fob[i*512 + k] * Mt[(size_t)k*512 + c];
    p += bob[i*512 + k] * Mt[(size_t)(512 + k)*512 + c];
  }
  float tot = block_sum_128(p, sh);
  if (threadIdx.x == 0) g_bmid[i*512 + c] = tot + mb[i*512 + c];
}

// ---------------- host orchestration ----------------------------------------
extern "C" void kernel_launch(void* const* d_in, const int* in_sizes, int n_in,
                              void* d_out, int out_size)
{
  const float* slots     = (const float*)d_in[0];
  const float* keep      = (const float*)d_in[1];
  const float* attn      = (const float*)d_in[2];
  const float* pm1_w     = (const float*)d_in[5];
  const float* pm1_b     = (const float*)d_in[6];
  const float* pm2_w     = (const float*)d_in[7];
  const float* pm2_b     = (const float*)d_in[8];
  const float* fwd_ln_g  = (const float*)d_in[9];
  const float* fwd_ln_b  = (const float*)d_in[10];
  const float* fwd_in_w  = (const float*)d_in[11];
  const float* fwd_in_b  = (const float*)d_in[12];
  const float* fwd_out_w = (const float*)d_in[13];
  const float* fwd_out_b = (const float*)d_in[14];
  const float* bwd_ln_g  = (const float*)d_in[15];
  const float* bwd_ln_b  = (const float*)d_in[16];
  const float* bwd_in_w  = (const float*)d_in[17];
  const float* bwd_in_b  = (const float*)d_in[18];
  const float* bwd_out_w = (const float*)d_in[19];
  const float* bwd_out_b = (const float*)d_in[20];
  const float* merge_w   = (const float*)d_in[21];
  const float* merge_b   = (const float*)d_in[22];
  const float* norm_g    = (const float*)d_in[23];
  const float* norm_b    = (const float*)d_in[24];
  const float* ffn_ln_g  = (const float*)d_in[25];
  const float* ffn_ln_b  = (const float*)d_in[26];
  const float* ffn1_w    = (const float*)d_in[27];
  const float* ffn1_b    = (const float*)d_in[28];
  const float* ffn2_w    = (const float*)d_in[29];
  const float* ffn2_b    = (const float*)d_in[30];
  float* out = (float*)d_out;

  float *xg, *res, *cent, *bcat, *bmid, *bf1, *zb;
  __half *ench, *lnfh, *xh, *hh, *wcath, *wf1h, *wmidh, *ffn2h, *pm1h, *pm2h, *fowh, *bowh, *mrgh;
  cudaGetSymbolAddress((void**)&xg,   g_x);
  cudaGetSymbolAddress((void**)&res,  g_res);
  cudaGetSymbolAddress((void**)&cent, g_cent);
  cudaGetSymbolAddress((void**)&ench, g_enc_h);
  cudaGetSymbolAddress((void**)&lnfh, g_lnf_h);
  cudaGetSymbolAddress((void**)&xh,   g_x_h);
  cudaGetSymbolAddress((void**)&hh,   g_h_h);
  cudaGetSymbolAddress((void**)&wcath,g_wcat_h);
  cudaGetSymbolAddress((void**)&wf1h, g_wf1_h);
  cudaGetSymbolAddress((void**)&wmidh,g_wmid_h);
  cudaGetSymbolAddress((void**)&ffn2h,g_ffn2_h);
  cudaGetSymbolAddress((void**)&pm1h, g_pm1_h);
  cudaGetSymbolAddress((void**)&pm2h, g_pm2_h);
  cudaGetSymbolAddress((void**)&fowh, g_fow_h);
  cudaGetSymbolAddress((void**)&bowh, g_bow_h);
  cudaGetSymbolAddress((void**)&mrgh, g_mrg_h);
  cudaGetSymbolAddress((void**)&bcat, g_bcat);
  cudaGetSymbolAddress((void**)&bmid, g_bmid);
  cudaGetSymbolAddress((void**)&bf1,  g_bf1);
  cudaGetSymbolAddress((void**)&zb,   g_zero);

  float* cent_out = nullptr;
  if ((long long)out_size >= (long long)Mz*Dz + (long long)Mz*2)
    cent_out = out + (size_t)Mz*Dz;

  const dim3 blk(128);

  // ---- weight conversion + precompute ----
  f2h_kernel<<<(256*512)/256, 256>>>(pm1_w, pm1h, 256*512);
  f2h_kernel<<<(512*512)/256, 256>>>(pm2_w, pm2h, 512*512);
  f2h_kernel<<<(2*2048*512)/256, 256>>>(ffn2_w, ffn2h, 2*2048*512);
  f2h_kernel<<<(2*1024*512)/256, 256>>>(fwd_out_w, fowh, 2*1024*512);
  f2h_kernel<<<(2*1024*512)/256, 256>>>(bwd_out_w, bowh, 2*1024*512);
  f2h_kernel<<<(2*1024*512)/256, 256>>>(merge_w, mrgh, 2*1024*512);
  build_wcat<<<16384, 256>>>(fwd_in_w, bwd_in_w, fwd_ln_g, bwd_ln_g);
  build_bcat<<<dim3(4096,2), 128>>>(fwd_in_w, bwd_in_w, fwd_ln_b, bwd_ln_b, fwd_in_b, bwd_in_b);
  build_wf1<<<8192, 256>>>(ffn1_w, ffn_ln_g);
  build_bf1<<<dim3(2048,2), 128>>>(ffn1_w, ffn_ln_b, ffn1_b);
  for (int i = 0; i < Lz; i++){
    // wmid rows 0..1023 = Wfo(1024x512) @ Mt
    gemm_h<0,false,false><<<dim3(4,8), blk, DSMEM_BYTES>>>(
        fowh + (size_t)i*1024*512, 512, 512,
        fowh, 512, 512,
        mrgh + (size_t)i*1024*512, 512, zb,
        nullptr, 0, nullptr,
        nullptr, wmidh + (size_t)i*2560*512, 512);
    // wmid rows 1024..2047 = Wbo(1024x512) @ Mb
    gemm_h<0,false,false><<<dim3(4,8), blk, DSMEM_BYTES>>>(
        bowh + (size_t)i*1024*512, 512, 512,
        bowh, 512, 512,
        mrgh + (size_t)i*1024*512 + (size_t)512*512, 512, zb,
        nullptr, 0, nullptr,
        nullptr, wmidh + (size_t)i*2560*512 + (size_t)1024*512, 512);
  }
  build_wmid_sum<<<2048, 256>>>(merge_w);
  build_bmid<<<dim3(512,2), 128>>>(merge_w, merge_b, fwd_out_b, bwd_out_b);

  // ---- positional encoding path ----
  centroid_kernel<<<Mz, 256>>>(attn, cent, cent_out);
  enc_kernel_h<<<Mz, 256>>>(cent, ench);
  gemm_h<1,false,false><<<dim3(4,128), blk, DSMEM_BYTES>>>(
      ench, 256, 256, ench, 256, 256, pm1h, 512, pm1_b,
      nullptr, 0, nullptr, nullptr, lnfh, 512);
  gemm_h<0,true,false><<<dim3(4,128), blk, DSMEM_BYTES>>>(
      lnfh, 512, 512, lnfh, 512, 512, pm2h, 512, pm2_b,
      slots, 512, nullptr, xg, xh, 512);

  // ---- layers ----
  for (int i = 0; i < Lz; i++){
    ln_plain_h<<<Mz, 128>>>(xg, lnfh);
    // fused fwd+bwd in-proj with GLU epilogue (N=4096)
    gemm_h<2,false,false><<<dim3(32,128), blk, DSMEM_BYTES>>>(
        lnfh, 512, 512, lnfh, 512, 512,
        wcath + (size_t)i*512*4096, 4096, bcat + (size_t)i*4096,
        nullptr, 0, nullptr, nullptr, hh, 2048);
    // fused out-proj + merge + residual: res = x + [hh | xh] @ Wmid + bmid
    gemm_h<0,true,false><<<dim3(4,128), blk, DSMEM_BYTES>>>(
        hh, 2048, 2048, xh, 512, 2560,
        wmidh + (size_t)i*2560*512, 512, bmid + (size_t)i*512,
        xg, 512, nullptr, res, nullptr, 512);
    ln_chain2_h<<<Mz, 128>>>(res, norm_g + i*Dz, norm_b + i*Dz, xg, xh, lnfh);
    // ffn1 with gelu (N=2048)
    gemm_h<1,false,false><<<dim3(16,128), blk, DSMEM_BYTES>>>(
        lnfh, 512, 512, lnfh, 512, 512,
        wf1h + (size_t)i*512*2048, 2048, bf1 + (size_t)i*2048,
        nullptr, 0, nullptr, nullptr, hh, 2048);
    // ffn2 + residual + mask
    if (i == Lz-1){
      gemm_h<0,true,true><<<dim3(4,128), blk, DSMEM_BYTES>>>(
          hh, 2048, 2048, hh, 2048, 2048,
          ffn2h + (size_t)i*2048*512, 512, ffn2_b + (size_t)i*512,
          xg, 512, keep, out, nullptr, 512);
    } else {
      gemm_h<0,true,true><<<dim3(4,128), blk, DSMEM_BYTES>>>(
          hh, 2048, 2048, hh, 2048, 2048,
          ffn2h + (size_t)i*2048*512, 512, ffn2_b + (size_t)i*512,
          xg, 512, keep, xg, xh, 512);
    }
  }
}